// round 14
// baseline (speedup 1.0000x reference)
#include <cuda_runtime.h>

// EHD layer v12 (8 px/thread, 64-wide index tile):
//   3x3 conv (8 filters) -> argmax+thresh -> byte-packed one-hot ->
//   separable 5x5 box sum -> magic-number unpack -> out[B,9,1018,1018].
//
// v12 vs v9 (196us):
//  - thread owns 8 horizontal px (index tile 64x32, output 60x28): halo
//    overcompute 1.31x -> 1.22x, per-px fixed costs (mask loads, shfl
//    edges, argmax setup, addressing) ~halved.
//  - conv in two 4-px groups (cols 0..5 then 4..9) to cap live regs.
//  - launch_bounds(256,4): 64-reg ILP headroom, 4 CTAs/SM.

#define NOR    8
#define NBINS  9
#define OUT_H  1018
#define OUT_W  1018
#define THRESH 0.9f

#define TW  60            // output tile width
#define TH  28            // output tile height
#define ITW 64            // index tile width
#define ITH 32            // index tile height

#define NTHREADS 256

typedef unsigned long long u64;

__constant__ float c_masks[NOR * 9];

__device__ __forceinline__ float cnt_scale(unsigned word, int byte_sel) {
    // word's byte[byte_sel] = count in 0..25 -> count * fl(1/25), exact
    const unsigned bits = __byte_perm(word, 0x4B000000u, 0x7440 | byte_sel);
    return fmaf(__int_as_float(bits), (1.0f / 25.0f),
                -(8388608.0f * (1.0f / 25.0f)));
}

__global__ __launch_bounds__(NTHREADS, 4)
void ehd_fused_kernel(const float* __restrict__ x,
                      float* __restrict__ out)
{
    __shared__ u64 s_h[ITH][66];  // horizontal 5-sums; stride 66 (even) keeps
                                  // quad columns 16B-aligned. cols 60..63 junk.

    const int tid  = threadIdx.x;
    const int lane = tid & 31;
    const int ox   = blockIdx.x * TW;
    const int oy   = blockIdx.y * TH;
    const int b    = blockIdx.z;

    const int r  = tid >> 3;          // index row within tile (0..31)
    const int c0 = (tid & 7) << 3;    // index col group (0,8,...,56)
    const int gx = ox + c0;           // mult of 4 (ox = 60*bx)
    const int gy = oy + r;

    const float* xb = x + (size_t)b * (1024 * 1024);

    // ---- stage A: 3x10 input window. Own 8 cols via 2x LDG.128; cols 8..9
    // borrowed from lane+1 (its cols 0..1) via shfl, LDG.64 fallback at
    // group edges (lane&7==7 -> lane+1 is a different row). ----
    float w[3][10];
    if (ox + 66 <= 1024 && oy + 34 <= 1024) {
        // fast path (CTA-uniform -> warp-converged shfl)
#pragma unroll
        for (int j = 0; j < 3; j++) {
            const float* row = xb + (gy + j) * 1024 + gx;
            const float4 a = *(const float4*)row;
            const float4 bq = *(const float4*)(row + 4);
            w[j][0] = a.x;  w[j][1] = a.y;  w[j][2] = a.z;  w[j][3] = a.w;
            w[j][4] = bq.x; w[j][5] = bq.y; w[j][6] = bq.z; w[j][7] = bq.w;
        }
        const bool edge = ((lane & 7) == 7);
#pragma unroll
        for (int j = 0; j < 3; j++) {
            const float t0 = __shfl_down_sync(0xFFFFFFFFu, w[j][0], 1);
            const float t1 = __shfl_down_sync(0xFFFFFFFFu, w[j][1], 1);
            if (edge) {
                const float2 e = *(const float2*)(xb + (gy + j) * 1024 + gx + 8);
                w[j][8] = e.x; w[j][9] = e.y;
            } else {
                w[j][8] = t0; w[j][9] = t1;
            }
        }
    } else {
        // slow path (edge tiles): per-element predicated, zero-fill OOB.
        // OOB zeros only feed index px whose outputs are clipped below.
#pragma unroll
        for (int j = 0; j < 3; j++) {
            const int yy = gy + j;
            const bool yv = (yy < 1024);
            const float* row = xb + yy * 1024 + gx;
#pragma unroll
            for (int k = 0; k < 10; k++)
                w[j][k] = (yv && (gx + k < 1024)) ? row[k] : 0.0f;
        }
    }

    // ---- stage B: conv + argmax + threshold, 8 px in two 4-px groups ----
    u64 oh[8];
#pragma unroll
    for (int grp = 0; grp < 2; grp++) {
        const int base = grp << 2;     // px base: 0 or 4 (cols base..base+5)
        float best[4];
        int   bi[4];
#pragma unroll
        for (int q = 0; q < 4; q++) { best[q] = -3.4e38f; bi[q] = 0; }

#pragma unroll
        for (int f = 0; f < NOR; f++) {
            const float m0 = c_masks[f * 9 + 0], m1 = c_masks[f * 9 + 1], m2 = c_masks[f * 9 + 2];
            const float m3 = c_masks[f * 9 + 3], m4 = c_masks[f * 9 + 4], m5 = c_masks[f * 9 + 5];
            const float m6 = c_masks[f * 9 + 6], m7 = c_masks[f * 9 + 7], m8 = c_masks[f * 9 + 8];
#pragma unroll
            for (int q = 0; q < 4; q++) {
                const int col = base + q;
                float acc = w[0][col] * m0;
                acc = fmaf(w[0][col + 1], m1, acc);
                acc = fmaf(w[0][col + 2], m2, acc);
                acc = fmaf(w[1][col    ], m3, acc);
                acc = fmaf(w[1][col + 1], m4, acc);
                acc = fmaf(w[1][col + 2], m5, acc);
                acc = fmaf(w[2][col    ], m6, acc);
                acc = fmaf(w[2][col + 1], m7, acc);
                acc = fmaf(w[2][col + 2], m8, acc);
                // strict > keeps FIRST max (jnp.argmax tie-break)
                if (acc > best[q]) { best[q] = acc; bi[q] = f; }
            }
        }
#pragma unroll
        for (int q = 0; q < 4; q++) {
            const int idx = (best[q] < THRESH) ? NOR : bi[q];
            // bins 0..7 -> one byte of a u64; bin 8 (no-edge) -> 0 (implicit)
            oh[base + q] = (idx < NOR) ? (1ULL << (idx << 3)) : 0ULL;
        }
    }

    // ---- stage C: horizontal 5-tap; cols 4..7 use in-register neighbors,
    // cols 8..11 (for h4..h7) come from lane+1's oh[0..3] via shfl ----
    const bool has_nbr = ((lane & 7) != 7);
    u64 n[4];
#pragma unroll
    for (int q = 0; q < 4; q++) {
        const u64 t = __shfl_down_sync(0xFFFFFFFFu, oh[q], 1);
        n[q] = has_nbr ? t : 0ULL;   // h[60..63] junk for edge group: unused
    }
    u64 h[8];
    h[0] = oh[0] + oh[1] + oh[2] + oh[3] + oh[4];
#pragma unroll
    for (int q = 1; q < 4; q++)  h[q] = h[q - 1] - oh[q - 1] + oh[q + 4];
#pragma unroll
    for (int q = 4; q < 8; q++)  h[q] = h[q - 1] - oh[q - 1] + n[q - 4];
    {
        ulonglong2* dst = (ulonglong2*)&s_h[r][c0];
        dst[0] = make_ulonglong2(h[0], h[1]);
        dst[1] = make_ulonglong2(h[2], h[3]);
        dst[2] = make_ulonglong2(h[4], h[5]);
        dst[3] = make_ulonglong2(h[6], h[7]);
    }
    __syncthreads();   // the only barrier

    // ---- stage D: vertical 5-tap on column QUADS, unpack, float2 stores ----
    // units: 28 rows x 15 quads = 420; two passes over 256 threads.
    const size_t plane = (size_t)OUT_H * OUT_W;
    float* ob = out + (size_t)b * NBINS * plane;
#pragma unroll
    for (int it = 0; it < 2; it++) {
        const int u = tid + it * NTHREADS;
        if (u < 15 * TH) {
            const int rr = u / 15;
            const int qq = u - rr * 15;
            const int cc = qq << 2;
            const int oyy = oy + rr, oxx = ox + cc;
            if (oyy < OUT_H && oxx < OUT_W) {
                u64 v[4] = {0ULL, 0ULL, 0ULL, 0ULL};
#pragma unroll
                for (int j = 0; j < 5; j++) {
                    const ulonglong2 a  = *(const ulonglong2*)&s_h[rr + j][cc];
                    const ulonglong2 bq = *(const ulonglong2*)&s_h[rr + j][cc + 2];
                    v[0] += a.x; v[1] += a.y; v[2] += bq.x; v[3] += bq.y;
                }
                unsigned lo[4], hi[4];
#pragma unroll
                for (int q = 0; q < 4; q++) {
                    lo[q] = (unsigned)v[q]; hi[q] = (unsigned)(v[q] >> 32);
                }
                float* p = ob + (size_t)oyy * OUT_W + oxx;

                if (oxx + 3 < OUT_W) {
                    // fast quad: 2x float2 per bin (8B align always holds;
                    // 16B does NOT on odd rows since OUT_W=1018)
#pragma unroll
                    for (int bin = 0; bin < 8; bin++) {
                        float2 oa, obq;
                        oa.x  = cnt_scale((bin < 4) ? lo[0] : hi[0], bin & 3);
                        oa.y  = cnt_scale((bin < 4) ? lo[1] : hi[1], bin & 3);
                        obq.x = cnt_scale((bin < 4) ? lo[2] : hi[2], bin & 3);
                        obq.y = cnt_scale((bin < 4) ? lo[3] : hi[3], bin & 3);
                        float* q8 = p + (size_t)bin * plane;
                        *(float2*)q8       = oa;
                        *(float2*)(q8 + 2) = obq;
                    }
                    float2 o8a, o8b;
                    o8a.x = cnt_scale(25u - __dp4a(lo[0], 0x01010101u, __dp4a(hi[0], 0x01010101u, 0u)), 0);
                    o8a.y = cnt_scale(25u - __dp4a(lo[1], 0x01010101u, __dp4a(hi[1], 0x01010101u, 0u)), 0);
                    o8b.x = cnt_scale(25u - __dp4a(lo[2], 0x01010101u, __dp4a(hi[2], 0x01010101u, 0u)), 0);
                    o8b.y = cnt_scale(25u - __dp4a(lo[3], 0x01010101u, __dp4a(hi[3], 0x01010101u, 0u)), 0);
                    float* q8 = p + (size_t)8 * plane;
                    *(float2*)q8       = o8a;
                    *(float2*)(q8 + 2) = o8b;
                } else {
                    // edge quad (last column tile only): per-element
#pragma unroll
                    for (int q = 0; q < 4; q++) {
                        if (oxx + q < OUT_W) {
#pragma unroll
                            for (int bin = 0; bin < 8; bin++)
                                p[(size_t)bin * plane + q] =
                                    cnt_scale((bin < 4) ? lo[q] : hi[q], bin & 3);
                            const unsigned s8 =
                                __dp4a(lo[q], 0x01010101u, __dp4a(hi[q], 0x01010101u, 0u));
                            p[(size_t)8 * plane + q] = cnt_scale(25u - s8, 0);
                        }
                    }
                }
            }
        }
    }
}

extern "C" void kernel_launch(void* const* d_in, const int* in_sizes, int n_in,
                              void* d_out, int out_size)
{
    const float* x     = (const float*)d_in[0];   // [B,1,1024,1024]
    const float* masks = (const float*)d_in[1];   // [8,1,3,3]
    float* out = (float*)d_out;                   // [B,9,1018,1018]

    const int batch = in_sizes[0] / (1024 * 1024);

    // masks -> constant bank (device-to-device async copy: graph-capturable)
    cudaMemcpyToSymbolAsync(c_masks, masks, NOR * 9 * sizeof(float), 0,
                            cudaMemcpyDeviceToDevice);

    dim3 grid((OUT_W + TW - 1) / TW, (OUT_H + TH - 1) / TH, batch);
    ehd_fused_kernel<<<grid, NTHREADS>>>(x, out);
}

// round 15
// speedup vs baseline: 1.0800x; 1.0800x over previous
#include <cuda_runtime.h>

// EHD layer v13 (= v9 + sliding row-pair stage D):
//   3x3 conv (8 filters) -> argmax+thresh -> byte-packed one-hot ->
//   separable 5x5 box sum -> magic-number unpack -> out[B,9,1018,1018].
//
// v13 vs v9 (196us best):
//  - stage D: thread owns a 2x2 output block. Vertical 5-tap slides:
//    v(r+1) = v(r) - h(r) + h(r+5). Per 4 px: 6 LDS.128 + 12 u64 adds
//    (was 10 + 16), single shift/mask pass (rp=tid>>4, cp=tid&15).
//  - stages A/B/C identical to v9: 48 regs, occ 5, one barrier.

#define NOR    8
#define NBINS  9
#define OUT_H  1018
#define OUT_W  1018
#define THRESH 0.9f

#define T   28            // output tile
#define IT  32            // index tile (T+4)

#define NTHREADS 256

typedef unsigned long long u64;

__constant__ float c_masks[NOR * 9];

__device__ __forceinline__ float cnt_scale(unsigned word, int byte_sel) {
    // word's byte[byte_sel] = count in 0..25 -> count * fl(1/25), exact
    const unsigned bits = __byte_perm(word, 0x4B000000u, 0x7440 | byte_sel);
    return fmaf(__int_as_float(bits), (1.0f / 25.0f),
                -(8388608.0f * (1.0f / 25.0f)));
}

__global__ __launch_bounds__(NTHREADS, 5)
void ehd_fused_kernel(const float* __restrict__ x,
                      float* __restrict__ out)
{
    __shared__ u64 s_h[IT][36];   // horizontal 5-sums (16B-aligned even cols)

    const int tid  = threadIdx.x;
    const int lane = tid & 31;
    const int ox   = blockIdx.x * T;
    const int oy   = blockIdx.y * T;
    const int b    = blockIdx.z;

    const int r  = tid >> 3;          // index row within tile (0..31)
    const int c0 = (tid & 7) << 2;    // index col group (0,4,...,28)
    const int gx = ox + c0;           // global col of first px (mult of 4)
    const int gy = oy + r;            // global row of index px

    const float* xb = x + (size_t)b * (1024 * 1024);

    // ---- stage A: load 3x6 input window straight from global ----
    float w[3][6];
    if (ox + 34 <= 1024 && oy + 34 <= 1024) {
        // fast path: whole 34x34 input footprint in-bounds (36/37 tiles each way)
#pragma unroll
        for (int j = 0; j < 3; j++) {
            const float* row = xb + (gy + j) * 1024 + gx;
            const float4 a = *(const float4*)row;       // gx multiple of 4
            const float2 bb = *(const float2*)(row + 4);
            w[j][0] = a.x; w[j][1] = a.y; w[j][2] = a.z;
            w[j][3] = a.w; w[j][4] = bb.x; w[j][5] = bb.y;
        }
    } else {
        // slow path (edge tiles): per-element predicated, zero-fill OOB.
        // OOB zeros only feed index px whose outputs are clipped below.
#pragma unroll
        for (int j = 0; j < 3; j++) {
            const int yy = gy + j;
            const bool yv = (yy < 1024);
            const float* row = xb + yy * 1024 + gx;
#pragma unroll
            for (int k = 0; k < 6; k++)
                w[j][k] = (yv && (gx + k < 1024)) ? row[k] : 0.0f;
        }
    }

    // ---- stage B: conv (8 filters) + argmax + threshold, 4 horizontal px ----
    float best[4];
    int   bi[4];
#pragma unroll
    for (int q = 0; q < 4; q++) { best[q] = -3.4e38f; bi[q] = 0; }

#pragma unroll
    for (int f = 0; f < NOR; f++) {
        const float m0 = c_masks[f * 9 + 0], m1 = c_masks[f * 9 + 1], m2 = c_masks[f * 9 + 2];
        const float m3 = c_masks[f * 9 + 3], m4 = c_masks[f * 9 + 4], m5 = c_masks[f * 9 + 5];
        const float m6 = c_masks[f * 9 + 6], m7 = c_masks[f * 9 + 7], m8 = c_masks[f * 9 + 8];
#pragma unroll
        for (int q = 0; q < 4; q++) {
            float acc = w[0][q] * m0;
            acc = fmaf(w[0][q + 1], m1, acc);
            acc = fmaf(w[0][q + 2], m2, acc);
            acc = fmaf(w[1][q    ], m3, acc);
            acc = fmaf(w[1][q + 1], m4, acc);
            acc = fmaf(w[1][q + 2], m5, acc);
            acc = fmaf(w[2][q    ], m6, acc);
            acc = fmaf(w[2][q + 1], m7, acc);
            acc = fmaf(w[2][q + 2], m8, acc);
            // strict > keeps FIRST max (jnp.argmax tie-break)
            if (acc > best[q]) { best[q] = acc; bi[q] = f; }
        }
    }

    // byte-packed one-hot: bins 0..7 -> one byte of a u64; bin 8 implicit
    u64 oh[4];
#pragma unroll
    for (int q = 0; q < 4; q++) {
        const int idx = (best[q] < THRESH) ? NOR : bi[q];
        oh[q] = (idx < NOR) ? (1ULL << (idx << 3)) : 0ULL;
    }

    // ---- stage C: horizontal 5-tap via shfl (neighbor quad = lane+1) ----
    const bool has_nbr = ((lane & 7) != 7);
    u64 n[4];
#pragma unroll
    for (int q = 0; q < 4; q++) {
        const u64 t = __shfl_down_sync(0xFFFFFFFFu, oh[q], 1);
        n[q] = has_nbr ? t : 0ULL;
    }
    const u64 h0 = oh[0] + oh[1] + oh[2] + oh[3] + n[0];
    const u64 h1 = h0 - oh[0] + n[1];
    const u64 h2 = h1 - oh[1] + n[2];
    const u64 h3 = h2 - oh[2] + n[3];
    {
        ulonglong2* dst = (ulonglong2*)&s_h[r][c0];
        dst[0] = make_ulonglong2(h0, h1);
        dst[1] = make_ulonglong2(h2, h3);
    }
    __syncthreads();   // the only barrier

    // ---- stage D: 2x2 output block per thread, sliding vertical 5-tap ----
    // rp = tid>>4 (row pair), cp = tid&15 (col pair); active: rp<14, cp<14.
    // v(r+1) = v(r) - h(r) + h(r+5): 6 LDS.128 + 12 u64 adds per 4 px.
    {
        const int rp = tid >> 4;
        const int cp = tid & 15;
        const int rr = rp << 1;
        const int cc = cp << 1;
        const int oyy = oy + rr, oxx = ox + cc;
        if (rp < 14 && cp < 14 && oyy < OUT_H && oxx + 1 < OUT_W) {
            const ulonglong2 q0 = *(const ulonglong2*)&s_h[rr    ][cc];
            const ulonglong2 q1 = *(const ulonglong2*)&s_h[rr + 1][cc];
            const ulonglong2 q2 = *(const ulonglong2*)&s_h[rr + 2][cc];
            const ulonglong2 q3 = *(const ulonglong2*)&s_h[rr + 3][cc];
            const ulonglong2 q4 = *(const ulonglong2*)&s_h[rr + 4][cc];
            const ulonglong2 q5 = *(const ulonglong2*)&s_h[rr + 5][cc];

            // row rr sums (cols cc, cc+1)
            const u64 va0 = q0.x + q1.x + q2.x + q3.x + q4.x;
            const u64 va1 = q0.y + q1.y + q2.y + q3.y + q4.y;
            // row rr+1 sums (slide)
            const u64 vb0 = va0 - q0.x + q5.x;
            const u64 vb1 = va1 - q0.y + q5.y;

            const unsigned alo0 = (unsigned)va0, ahi0 = (unsigned)(va0 >> 32);
            const unsigned alo1 = (unsigned)va1, ahi1 = (unsigned)(va1 >> 32);
            const unsigned blo0 = (unsigned)vb0, bhi0 = (unsigned)(vb0 >> 32);
            const unsigned blo1 = (unsigned)vb1, bhi1 = (unsigned)(vb1 >> 32);

            const size_t plane = (size_t)OUT_H * OUT_W;
            float* pa = out + (size_t)b * NBINS * plane + (size_t)oyy * OUT_W + oxx;
            const bool row2 = (oyy + 1 < OUT_H);   // rr+1 valid (rr<=26 -> oyy+1<=oy+27, always in tile; only clip at image edge)

#pragma unroll
            for (int bin = 0; bin < 8; bin++) {
                const int sel = bin & 3;
                float2 va, vb;
                va.x = cnt_scale((bin < 4) ? alo0 : ahi0, sel);
                va.y = cnt_scale((bin < 4) ? alo1 : ahi1, sel);
                float* qp = pa + (size_t)bin * plane;
                *(float2*)qp = va;
                if (row2) {
                    vb.x = cnt_scale((bin < 4) ? blo0 : bhi0, sel);
                    vb.y = cnt_scale((bin < 4) ? blo1 : bhi1, sel);
                    *(float2*)(qp + OUT_W) = vb;
                }
            }
            // bin 8 = 25 - sum of the other 8 counts
            float2 v8a;
            v8a.x = cnt_scale(25u - __dp4a(alo0, 0x01010101u, __dp4a(ahi0, 0x01010101u, 0u)), 0);
            v8a.y = cnt_scale(25u - __dp4a(alo1, 0x01010101u, __dp4a(ahi1, 0x01010101u, 0u)), 0);
            float* q8 = pa + (size_t)8 * plane;
            *(float2*)q8 = v8a;
            if (row2) {
                float2 v8b;
                v8b.x = cnt_scale(25u - __dp4a(blo0, 0x01010101u, __dp4a(bhi0, 0x01010101u, 0u)), 0);
                v8b.y = cnt_scale(25u - __dp4a(blo1, 0x01010101u, __dp4a(bhi1, 0x01010101u, 0u)), 0);
                *(float2*)(q8 + OUT_W) = v8b;
            }
        }
    }
}

extern "C" void kernel_launch(void* const* d_in, const int* in_sizes, int n_in,
                              void* d_out, int out_size)
{
    const float* x     = (const float*)d_in[0];   // [B,1,1024,1024]
    const float* masks = (const float*)d_in[1];   // [8,1,3,3]
    float* out = (float*)d_out;                   // [B,9,1018,1018]

    const int batch = in_sizes[0] / (1024 * 1024);

    // masks -> constant bank (device-to-device async copy: graph-capturable)
    cudaMemcpyToSymbolAsync(c_masks, masks, NOR * 9 * sizeof(float), 0,
                            cudaMemcpyDeviceToDevice);

    dim3 grid((OUT_W + T - 1) / T, (OUT_H + T - 1) / T, batch);
    ehd_fused_kernel<<<grid, NTHREADS>>>(x, out);
}